// round 6
// baseline (speedup 1.0000x reference)
#include <cuda_runtime.h>

#define BQ 4
#define NP 8192
#define SQ 2048
#define CF 16
#define KN 32
constexpr int    P    = BQ * SQ * KN;        // 262144 points
constexpr float  R2   = 0.25f;
constexpr double EPSD = 1e-5;
constexpr double INVP = 1.0 / (double)P;

// ---------------- scratch ----------------
__device__ int    g_valid[BQ * SQ];
__device__ float  g_featT[(size_t)BQ * NP * CF];   // [b][j][c] point-major
__device__ float  g_y1[(size_t)P * 32];
__device__ float  g_y2[(size_t)P * 32];
__device__ float  g_y3[(size_t)P * 64];
// [0:32)sum1 [32:64)sq1 [64:96)sum2 [96:128)sq2 [128:192)sum3 [192:256)sq3
__device__ double g_stats[256];

// ---------------- f32x2 helpers ----------------
__device__ __forceinline__ unsigned long long pack2(float a, float b) {
    unsigned long long r;
    asm("mov.b64 %0, {%1, %2};" : "=l"(r) : "f"(a), "f"(b));
    return r;
}
__device__ __forceinline__ unsigned long long dup2(float a) {
    unsigned long long r;
    asm("mov.b64 %0, {%1, %1};" : "=l"(r) : "f"(a));
    return r;
}
__device__ __forceinline__ void fma2(unsigned long long& d,
                                     unsigned long long a, unsigned long long b) {
    asm("fma.rn.f32x2 %0, %1, %2, %0;" : "+l"(d) : "l"(a), "l"(b));
}
__device__ __forceinline__ float2 unpack2(unsigned long long v) {
    float lo, hi;
    asm("mov.b64 {%0, %1}, %2;" : "=f"(lo), "=f"(hi) : "l"(v));
    return make_float2(lo, hi);
}

// Warp transpose-fold (used only in k1).
__device__ __forceinline__ void warp_fold(float* s, float* t, int lane,
                                          float& osum, float& osq) {
    #pragma unroll
    for (int st = 0; st < 5; st++) {
        int wbit = 1 << st;
        bool hi = (lane & wbit) != 0;
        #pragma unroll
        for (int k = 0; k < (16 >> st); k++) {
            float slo = s[2 * k], shi = s[2 * k + 1];
            float ssend = hi ? slo : shi;
            float skeep = hi ? shi : slo;
            s[k] = skeep + __shfl_xor_sync(0xffffffffu, ssend, wbit);
            float tlo = t[2 * k], thi = t[2 * k + 1];
            float tsend = hi ? tlo : thi;
            float tkeep = hi ? thi : tlo;
            t[k] = tkeep + __shfl_xor_sync(0xffffffffu, tsend, wbit);
        }
    }
    osum = s[0]; osq = t[0];
}

// ---------------- prep: zero stats + transpose feat to point-major ----------
__global__ __launch_bounds__(256) void prep_kernel(const float* __restrict__ feat) {
    __shared__ float tile[16][65];
    int tid = threadIdx.x;
    if (blockIdx.x == 0) g_stats[tid] = 0.0;
    int b  = blockIdx.x >> 7;
    int j0 = (blockIdx.x & 127) * 64;
    const float* f = feat + (size_t)b * CF * NP;
    #pragma unroll
    for (int i = tid; i < 1024; i += 256) {
        int c = i >> 6, jj = i & 63;
        tile[c][jj] = f[(size_t)c * NP + j0 + jj];
    }
    __syncthreads();
    float* o = g_featT + ((size_t)b * NP + j0) * CF;
    #pragma unroll
    for (int i = tid; i < 1024; i += 256) {
        int jj = i >> 4, c = i & 15;
        o[i] = tile[c][jj];
    }
}

// ---------------- k1: ball query + gather + conv1 + stats1 -----------------
__global__ __launch_bounds__(256) void k1_kernel(
    const float* __restrict__ pc, const float* __restrict__ newpc,
    const float* __restrict__ w1, const float* __restrict__ b1)
{
    extern __shared__ float spc[];                 // 3*NP floats (96 KB)
    __shared__ unsigned long long swp[19 * 16];
    __shared__ unsigned long long sbp[16];
    __shared__ float bss[32], bsq[32];
    __shared__ int   sIdx[8][KN];

    int tid = threadIdx.x, lane = tid & 31, w = tid >> 5;
    int qb = blockIdx.x * 32;
    int b  = qb >> 11;

    const float4* src = (const float4*)(pc + (size_t)b * 3 * NP);
    float4* d4 = (float4*)spc;
    #pragma unroll 4
    for (int i = tid; i < (3 * NP) / 4; i += 256) d4[i] = src[i];
    for (int i = tid; i < 304; i += 256) {
        int ci = i >> 4, c2 = i & 15;
        swp[i] = pack2(w1[(2 * c2) * 19 + ci], w1[(2 * c2 + 1) * 19 + ci]);
    }
    if (tid < 16) sbp[tid] = pack2(b1[2 * tid], b1[2 * tid + 1]);
    if (tid < 32) { bss[tid] = 0.f; bsq[tid] = 0.f; }
    __syncthreads();

    #pragma unroll 1
    for (int qi = 0; qi < 4; qi++) {
        int q  = qb + w * 4 + qi;
        int sl = q & (SQ - 1);
        const float* np = newpc + (size_t)b * 3 * SQ + sl;
        float qx = np[0], qy = np[SQ], qz = np[2 * SQ];

        int count = 0, firstidx = 0;
        for (int j0 = 0; j0 < NP; j0 += 64) {
            int ja = j0 + lane, jb = ja + 32;
            float ax = spc[ja] - qx, ay = spc[NP + ja] - qy, az = spc[2 * NP + ja] - qz;
            float bx = spc[jb] - qx, by = spc[NP + jb] - qy, bz = spc[2 * NP + jb] - qz;
            bool ina = fmaf(ax, ax, fmaf(ay, ay, az * az)) < R2;
            bool inb = fmaf(bx, bx, fmaf(by, by, bz * bz)) < R2;
            unsigned ma = __ballot_sync(0xffffffffu, ina);
            unsigned mb = __ballot_sync(0xffffffffu, inb);
            if (ma | mb) {
                if (count == 0)
                    firstidx = ma ? (j0 + __ffs((int)ma) - 1)
                                  : (j0 + 32 + __ffs((int)mb) - 1);
                if (ina) {
                    int slot = count + __popc(ma & ((1u << lane) - 1u));
                    if (slot < KN) sIdx[w][slot] = ja;
                }
                int ca = count + __popc(ma);
                if (inb) {
                    int slot = ca + __popc(mb & ((1u << lane) - 1u));
                    if (slot < KN) sIdx[w][slot] = jb;
                }
                count = ca + __popc(mb);
                if (count >= KN) break;
            }
        }
        if (lane >= count) sIdx[w][lane] = firstidx;
        if (lane == 0) g_valid[q] = (count > 0) ? 1 : 0;
        __syncwarp();
        int j = sIdx[w][lane];
        __syncwarp();

        float x[19];
        x[0] = spc[j] - qx; x[1] = spc[NP + j] - qy; x[2] = spc[2 * NP + j] - qz;
        const float4* ft = (const float4*)(g_featT + ((size_t)b * NP + j) * CF);
        float4 f;
        f = ft[0]; x[3]  = f.x; x[4]  = f.y; x[5]  = f.z; x[6]  = f.w;
        f = ft[1]; x[7]  = f.x; x[8]  = f.y; x[9]  = f.z; x[10] = f.w;
        f = ft[2]; x[11] = f.x; x[12] = f.y; x[13] = f.z; x[14] = f.w;
        f = ft[3]; x[15] = f.x; x[16] = f.y; x[17] = f.z; x[18] = f.w;

        unsigned long long acc[16];
        #pragma unroll
        for (int c2 = 0; c2 < 16; c2++) acc[c2] = sbp[c2];
        #pragma unroll
        for (int i = 0; i < 19; i++) {
            unsigned long long xx = dup2(x[i]);
            const ulonglong2* wp = (const ulonglong2*)(swp + i * 16);
            #pragma unroll
            for (int c4 = 0; c4 < 8; c4++) {
                ulonglong2 wv = wp[c4];
                fma2(acc[2 * c4],     wv.x, xx);
                fma2(acc[2 * c4 + 1], wv.y, xx);
            }
        }
        float y[32], yq[32];
        #pragma unroll
        for (int c2 = 0; c2 < 16; c2++) {
            float2 u = unpack2(acc[c2]);
            y[2 * c2] = u.x; y[2 * c2 + 1] = u.y;
        }
        float4* dst = (float4*)(g_y1 + ((size_t)q * 32 + lane) * 32);
        #pragma unroll
        for (int c4 = 0; c4 < 8; c4++)
            dst[c4] = make_float4(y[4 * c4], y[4 * c4 + 1], y[4 * c4 + 2], y[4 * c4 + 3]);
        #pragma unroll
        for (int c = 0; c < 32; c++) yq[c] = y[c] * y[c];
        float osum, osq;
        warp_fold(y, yq, lane, osum, osq);
        atomicAdd(&bss[lane], osum);
        atomicAdd(&bsq[lane], osq);
    }
    __syncthreads();
    if (tid < 32) {
        atomicAdd(&g_stats[tid],      (double)bss[tid]);
        atomicAdd(&g_stats[32 + tid], (double)bsq[tid]);
    }
}

// ---------------- k2: BN1+ReLU + conv2 + stats2 (2-ch/thread, even/odd) -----
// 1024 blocks x 256 threads; tile = 256 points. Thread owns channels
// (c, c+16), c = tid&15; weights input-pair packed in regs (no dup).
__global__ __launch_bounds__(256) void k2_kernel(
    const float* __restrict__ w2, const float* __restrict__ b2,
    const float* __restrict__ gam, const float* __restrict__ bet)
{
    __shared__ float zp[256 * 32];      // [p][k] BN1+ReLU, 32 KB
    __shared__ float sa[32], sc[32];
    __shared__ float bss[32], bsq[32];
    int tid = threadIdx.x;
    if (tid < 32) {
        double m = g_stats[tid] * INVP;
        double v = g_stats[32 + tid] * INVP - m * m;
        double a = (double)gam[tid] / sqrt(v + EPSD);
        sa[tid] = (float)a;
        sc[tid] = (float)((double)bet[tid] - m * a);
        bss[tid] = 0.f; bsq[tid] = 0.f;
    }
    __syncthreads();

    int p0 = blockIdx.x * 256;
    const float4* y4 = (const float4*)(g_y1 + (size_t)p0 * 32);
    float4* z4 = (float4*)zp;
    #pragma unroll
    for (int it = 0; it < 8; it++) {
        int lf = it * 256 + tid;                  // [0, 2048)
        int c0 = (lf & 7) * 4;
        float4 v = y4[lf];
        v.x = fmaxf(fmaf(sa[c0 + 0], v.x, sc[c0 + 0]), 0.f);
        v.y = fmaxf(fmaf(sa[c0 + 1], v.y, sc[c0 + 1]), 0.f);
        v.z = fmaxf(fmaf(sa[c0 + 2], v.z, sc[c0 + 2]), 0.f);
        v.w = fmaxf(fmaf(sa[c0 + 3], v.w, sc[c0 + 3]), 0.f);
        z4[lf] = v;
    }

    int c  = tid & 15;                            // channels c, c+16
    int pg = tid >> 4;                            // 16 groups x 16 points
    unsigned long long wA[16], wB[16];
    #pragma unroll
    for (int k = 0; k < 16; k++) {
        wA[k] = pack2(w2[c * 32 + 2 * k],        w2[c * 32 + 2 * k + 1]);
        wB[k] = pack2(w2[(c + 16) * 32 + 2 * k], w2[(c + 16) * 32 + 2 * k + 1]);
    }
    float biasA = b2[c], biasB = b2[c + 16];
    __syncthreads();

    float ssA = 0.f, sqA = 0.f, ssB = 0.f, sqB = 0.f;
    #pragma unroll 2
    for (int t = 0; t < 16; t++) {
        int p = pg * 16 + t;
        const ulonglong2* r = (const ulonglong2*)(zp + p * 32);
        unsigned long long accA = 0, accB = 0;
        #pragma unroll
        for (int k = 0; k < 8; k++) {
            ulonglong2 lv = r[k];
            fma2(accA, wA[2 * k],     lv.x);
            fma2(accA, wA[2 * k + 1], lv.y);
            fma2(accB, wB[2 * k],     lv.x);
            fma2(accB, wB[2 * k + 1], lv.y);
        }
        float2 uA = unpack2(accA), uB = unpack2(accB);
        float yA = uA.x + uA.y + biasA;
        float yB = uB.x + uB.y + biasB;
        g_y2[(size_t)(p0 + p) * 32 + c]      = yA;
        g_y2[(size_t)(p0 + p) * 32 + c + 16] = yB;
        ssA += yA; sqA = fmaf(yA, yA, sqA);
        ssB += yB; sqB = fmaf(yB, yB, sqB);
    }
    atomicAdd(&bss[c], ssA);      atomicAdd(&bsq[c], sqA);
    atomicAdd(&bss[c + 16], ssB); atomicAdd(&bsq[c + 16], sqB);
    __syncthreads();
    if (tid < 32) {
        atomicAdd(&g_stats[64 + tid], (double)bss[tid]);
        atomicAdd(&g_stats[96 + tid], (double)bsq[tid]);
    }
}

// ---------------- k3: BN2+ReLU + conv3 (32->64) + stats3 (2-ch/thread) ------
// 1024 blocks x 256 threads; tile = 256 points. Thread owns (c, c+32), c=tid&31.
__global__ __launch_bounds__(256) void k3_kernel(
    const float* __restrict__ w3, const float* __restrict__ b3,
    const float* __restrict__ gam, const float* __restrict__ bet)
{
    __shared__ float zp[256 * 32];      // 32 KB
    __shared__ float sa[32], sc[32];
    __shared__ float bss[64], bsq[64];
    int tid = threadIdx.x;
    if (tid < 32) {
        double m = g_stats[64 + tid] * INVP;
        double v = g_stats[96 + tid] * INVP - m * m;
        double a = (double)gam[tid] / sqrt(v + EPSD);
        sa[tid] = (float)a;
        sc[tid] = (float)((double)bet[tid] - m * a);
    }
    if (tid < 64) { bss[tid] = 0.f; bsq[tid] = 0.f; }
    __syncthreads();

    int p0 = blockIdx.x * 256;
    const float4* y4 = (const float4*)(g_y2 + (size_t)p0 * 32);
    float4* z4 = (float4*)zp;
    #pragma unroll
    for (int it = 0; it < 8; it++) {
        int lf = it * 256 + tid;
        int c0 = (lf & 7) * 4;
        float4 v = y4[lf];
        v.x = fmaxf(fmaf(sa[c0 + 0], v.x, sc[c0 + 0]), 0.f);
        v.y = fmaxf(fmaf(sa[c0 + 1], v.y, sc[c0 + 1]), 0.f);
        v.z = fmaxf(fmaf(sa[c0 + 2], v.z, sc[c0 + 2]), 0.f);
        v.w = fmaxf(fmaf(sa[c0 + 3], v.w, sc[c0 + 3]), 0.f);
        z4[lf] = v;
    }

    int c  = tid & 31;                            // channels c, c+32
    int pg = tid >> 5;                            // 8 groups x 32 points
    unsigned long long wA[16], wB[16];
    #pragma unroll
    for (int k = 0; k < 16; k++) {
        wA[k] = pack2(w3[c * 32 + 2 * k],        w3[c * 32 + 2 * k + 1]);
        wB[k] = pack2(w3[(c + 32) * 32 + 2 * k], w3[(c + 32) * 32 + 2 * k + 1]);
    }
    float biasA = b3[c], biasB = b3[c + 32];
    __syncthreads();

    float ssA = 0.f, sqA = 0.f, ssB = 0.f, sqB = 0.f;
    #pragma unroll 2
    for (int t = 0; t < 32; t++) {
        int p = pg * 32 + t;
        const ulonglong2* r = (const ulonglong2*)(zp + p * 32);
        unsigned long long accA = 0, accB = 0;
        #pragma unroll
        for (int k = 0; k < 8; k++) {
            ulonglong2 lv = r[k];
            fma2(accA, wA[2 * k],     lv.x);
            fma2(accA, wA[2 * k + 1], lv.y);
            fma2(accB, wB[2 * k],     lv.x);
            fma2(accB, wB[2 * k + 1], lv.y);
        }
        float2 uA = unpack2(accA), uB = unpack2(accB);
        float yA = uA.x + uA.y + biasA;
        float yB = uB.x + uB.y + biasB;
        g_y3[(size_t)(p0 + p) * 64 + c]      = yA;
        g_y3[(size_t)(p0 + p) * 64 + c + 32] = yB;
        ssA += yA; sqA = fmaf(yA, yA, sqA);
        ssB += yB; sqB = fmaf(yB, yB, sqB);
    }
    atomicAdd(&bss[c], ssA);      atomicAdd(&bsq[c], sqA);
    atomicAdd(&bss[c + 32], ssB); atomicAdd(&bsq[c + 32], sqB);
    __syncthreads();
    if (tid < 64) {
        atomicAdd(&g_stats[128 + tid], (double)bss[tid]);
        atomicAdd(&g_stats[192 + tid], (double)bsq[tid]);
    }
}

// ---------------- k4: BN3+ReLU + valid mask + transpose to [B,64,S,K] ------
__global__ __launch_bounds__(256) void k4_kernel(
    float* __restrict__ out,
    const float* __restrict__ gam, const float* __restrict__ bet)
{
    __shared__ float tile[64 * 65];
    __shared__ float sa[64], sc[64];
    int tid = threadIdx.x;
    if (tid < 64) {
        double m = g_stats[128 + tid] * INVP;
        double v = g_stats[192 + tid] * INVP - m * m;
        double a = (double)gam[tid] / sqrt(v + EPSD);
        sa[tid] = (float)a;
        sc[tid] = (float)((double)bet[tid] - m * a);
    }
    __syncthreads();

    int pt0 = blockIdx.x * 64;
    int b   = pt0 >> 16;
    int w0  = pt0 & 65535;
    const float* srcp = g_y3 + (size_t)pt0 * 64;
    #pragma unroll
    for (int it = 0; it < 16; it++) {
        int flat = it * 256 + tid;
        int p = flat >> 6, c = flat & 63;
        float val = fmaxf(fmaf(sa[c], srcp[flat], sc[c]), 0.f);
        val *= (float)g_valid[(pt0 + p) >> 5];
        tile[p * 65 + c] = val;
    }
    __syncthreads();
    float* ob = out + (size_t)b * 64 * 65536 + w0;
    #pragma unroll
    for (int it = 0; it < 16; it++) {
        int flat = it * 256 + tid;
        int c = flat >> 6, p = flat & 63;
        ob[(size_t)c * 65536 + p] = tile[p * 65 + c];
    }
}

// ---------------- launch ---------------------------------------------------
extern "C" void kernel_launch(void* const* d_in, const int* in_sizes, int n_in,
                              void* d_out, int out_size)
{
    const float* pc   = (const float*)d_in[0];
    const float* feat = (const float*)d_in[1];
    const float* npc  = (const float*)d_in[2];
    const float* w1   = (const float*)d_in[3];
    const float* b1   = (const float*)d_in[4];
    const float* g1   = (const float*)d_in[5];
    const float* be1  = (const float*)d_in[6];
    const float* w2   = (const float*)d_in[7];
    const float* b2   = (const float*)d_in[8];
    const float* g2   = (const float*)d_in[9];
    const float* be2  = (const float*)d_in[10];
    const float* w3   = (const float*)d_in[11];
    const float* b3   = (const float*)d_in[12];
    const float* g3   = (const float*)d_in[13];
    const float* be3  = (const float*)d_in[14];
    float* out = (float*)d_out;

    cudaFuncSetAttribute(k1_kernel, cudaFuncAttributeMaxDynamicSharedMemorySize,
                         3 * NP * sizeof(float));

    prep_kernel<<<512, 256>>>(feat);
    k1_kernel<<<256, 256, 3 * NP * sizeof(float)>>>(pc, npc, w1, b1);
    k2_kernel<<<1024, 256>>>(w2, b2, g1, be1);
    k3_kernel<<<1024, 256>>>(w3, b3, g2, be2);
    k4_kernel<<<4096, 256>>>(out, g3, be3);
}

// round 8
// speedup vs baseline: 1.0287x; 1.0287x over previous
#include <cuda_runtime.h>

#define BQ 4
#define NP 8192
#define SQ 2048
#define CF 16
#define KN 32
constexpr int    P    = BQ * SQ * KN;        // 262144 points
constexpr float  R2   = 0.25f;
constexpr double EPSD = 1e-5;
constexpr double INVP = 1.0 / (double)P;

// ---------------- scratch ----------------
__device__ int    g_valid[BQ * SQ];
__device__ float  g_featT[(size_t)BQ * NP * CF];   // [b][j][c] point-major
__device__ float  g_y1[(size_t)P * 32];
__device__ float  g_y2[(size_t)P * 32];
__device__ float  g_y3[(size_t)P * 64];
// [0:32)sum1 [32:64)sq1 [64:96)sum2 [96:128)sq2 [128:192)sum3 [192:256)sq3
__device__ double g_stats[256];

// ---------------- f32x2 helpers ----------------
__device__ __forceinline__ unsigned long long pack2(float a, float b) {
    unsigned long long r;
    asm("mov.b64 %0, {%1, %2};" : "=l"(r) : "f"(a), "f"(b));
    return r;
}
__device__ __forceinline__ unsigned long long dup2(float a) {
    unsigned long long r;
    asm("mov.b64 %0, {%1, %1};" : "=l"(r) : "f"(a));
    return r;
}
__device__ __forceinline__ void fma2(unsigned long long& d,
                                     unsigned long long a, unsigned long long b) {
    asm("fma.rn.f32x2 %0, %1, %2, %0;" : "+l"(d) : "l"(a), "l"(b));
}
__device__ __forceinline__ float2 unpack2(unsigned long long v) {
    float lo, hi;
    asm("mov.b64 {%0, %1}, %2;" : "=f"(lo), "=f"(hi) : "l"(v));
    return make_float2(lo, hi);
}

// Warp transpose-fold (used only in k1).
__device__ __forceinline__ void warp_fold(float* s, float* t, int lane,
                                          float& osum, float& osq) {
    #pragma unroll
    for (int st = 0; st < 5; st++) {
        int wbit = 1 << st;
        bool hi = (lane & wbit) != 0;
        #pragma unroll
        for (int k = 0; k < (16 >> st); k++) {
            float slo = s[2 * k], shi = s[2 * k + 1];
            float ssend = hi ? slo : shi;
            float skeep = hi ? shi : slo;
            s[k] = skeep + __shfl_xor_sync(0xffffffffu, ssend, wbit);
            float tlo = t[2 * k], thi = t[2 * k + 1];
            float tsend = hi ? tlo : thi;
            float tkeep = hi ? thi : tlo;
            t[k] = tkeep + __shfl_xor_sync(0xffffffffu, tsend, wbit);
        }
    }
    osum = s[0]; osq = t[0];
}

// ---------------- prep: zero stats + transpose feat to point-major ----------
__global__ __launch_bounds__(256) void prep_kernel(const float* __restrict__ feat) {
    __shared__ float tile[16][65];
    int tid = threadIdx.x;
    if (blockIdx.x == 0) g_stats[tid] = 0.0;
    int b  = blockIdx.x >> 7;
    int j0 = (blockIdx.x & 127) * 64;
    const float* f = feat + (size_t)b * CF * NP;
    #pragma unroll
    for (int i = tid; i < 1024; i += 256) {
        int c = i >> 6, jj = i & 63;
        tile[c][jj] = f[(size_t)c * NP + j0 + jj];
    }
    __syncthreads();
    float* o = g_featT + ((size_t)b * NP + j0) * CF;
    #pragma unroll
    for (int i = tid; i < 1024; i += 256) {
        int jj = i >> 4, c = i & 15;
        o[i] = tile[c][jj];
    }
}

// ---------------- k1: ball query + gather + conv1 + stats1 -----------------
__global__ __launch_bounds__(256) void k1_kernel(
    const float* __restrict__ pc, const float* __restrict__ newpc,
    const float* __restrict__ w1, const float* __restrict__ b1)
{
    extern __shared__ float spc[];                 // 3*NP floats (96 KB)
    __shared__ unsigned long long swp[19 * 16];
    __shared__ unsigned long long sbp[16];
    __shared__ float bss[32], bsq[32];
    __shared__ int   sIdx[8][KN];

    int tid = threadIdx.x, lane = tid & 31, w = tid >> 5;
    int qb = blockIdx.x * 32;
    int b  = qb >> 11;

    const float4* src = (const float4*)(pc + (size_t)b * 3 * NP);
    float4* d4 = (float4*)spc;
    #pragma unroll 4
    for (int i = tid; i < (3 * NP) / 4; i += 256) d4[i] = src[i];
    for (int i = tid; i < 304; i += 256) {
        int ci = i >> 4, c2 = i & 15;
        swp[i] = pack2(w1[(2 * c2) * 19 + ci], w1[(2 * c2 + 1) * 19 + ci]);
    }
    if (tid < 16) sbp[tid] = pack2(b1[2 * tid], b1[2 * tid + 1]);
    if (tid < 32) { bss[tid] = 0.f; bsq[tid] = 0.f; }
    __syncthreads();

    #pragma unroll 1
    for (int qi = 0; qi < 4; qi++) {
        int q  = qb + w * 4 + qi;
        int sl = q & (SQ - 1);
        const float* np = newpc + (size_t)b * 3 * SQ + sl;
        float qx = np[0], qy = np[SQ], qz = np[2 * SQ];

        int count = 0, firstidx = 0;
        for (int j0 = 0; j0 < NP; j0 += 64) {
            int ja = j0 + lane, jb = ja + 32;
            float ax = spc[ja] - qx, ay = spc[NP + ja] - qy, az = spc[2 * NP + ja] - qz;
            float bx = spc[jb] - qx, by = spc[NP + jb] - qy, bz = spc[2 * NP + jb] - qz;
            bool ina = fmaf(ax, ax, fmaf(ay, ay, az * az)) < R2;
            bool inb = fmaf(bx, bx, fmaf(by, by, bz * bz)) < R2;
            unsigned ma = __ballot_sync(0xffffffffu, ina);
            unsigned mb = __ballot_sync(0xffffffffu, inb);
            if (ma | mb) {
                if (count == 0)
                    firstidx = ma ? (j0 + __ffs((int)ma) - 1)
                                  : (j0 + 32 + __ffs((int)mb) - 1);
                if (ina) {
                    int slot = count + __popc(ma & ((1u << lane) - 1u));
                    if (slot < KN) sIdx[w][slot] = ja;
                }
                int ca = count + __popc(ma);
                if (inb) {
                    int slot = ca + __popc(mb & ((1u << lane) - 1u));
                    if (slot < KN) sIdx[w][slot] = jb;
                }
                count = ca + __popc(mb);
                if (count >= KN) break;
            }
        }
        if (lane >= count) sIdx[w][lane] = firstidx;
        if (lane == 0) g_valid[q] = (count > 0) ? 1 : 0;
        __syncwarp();
        int j = sIdx[w][lane];
        __syncwarp();

        float x[19];
        x[0] = spc[j] - qx; x[1] = spc[NP + j] - qy; x[2] = spc[2 * NP + j] - qz;
        const float4* ft = (const float4*)(g_featT + ((size_t)b * NP + j) * CF);
        float4 f;
        f = ft[0]; x[3]  = f.x; x[4]  = f.y; x[5]  = f.z; x[6]  = f.w;
        f = ft[1]; x[7]  = f.x; x[8]  = f.y; x[9]  = f.z; x[10] = f.w;
        f = ft[2]; x[11] = f.x; x[12] = f.y; x[13] = f.z; x[14] = f.w;
        f = ft[3]; x[15] = f.x; x[16] = f.y; x[17] = f.z; x[18] = f.w;

        unsigned long long acc[16];
        #pragma unroll
        for (int c2 = 0; c2 < 16; c2++) acc[c2] = sbp[c2];
        #pragma unroll
        for (int i = 0; i < 19; i++) {
            unsigned long long xx = dup2(x[i]);
            const ulonglong2* wp = (const ulonglong2*)(swp + i * 16);
            #pragma unroll
            for (int c4 = 0; c4 < 8; c4++) {
                ulonglong2 wv = wp[c4];
                fma2(acc[2 * c4],     wv.x, xx);
                fma2(acc[2 * c4 + 1], wv.y, xx);
            }
        }
        float y[32], yq[32];
        #pragma unroll
        for (int c2 = 0; c2 < 16; c2++) {
            float2 u = unpack2(acc[c2]);
            y[2 * c2] = u.x; y[2 * c2 + 1] = u.y;
        }
        float4* dst = (float4*)(g_y1 + ((size_t)q * 32 + lane) * 32);
        #pragma unroll
        for (int c4 = 0; c4 < 8; c4++)
            dst[c4] = make_float4(y[4 * c4], y[4 * c4 + 1], y[4 * c4 + 2], y[4 * c4 + 3]);
        #pragma unroll
        for (int c = 0; c < 32; c++) yq[c] = y[c] * y[c];
        float osum, osq;
        warp_fold(y, yq, lane, osum, osq);
        atomicAdd(&bss[lane], osum);
        atomicAdd(&bsq[lane], osq);
    }
    __syncthreads();
    if (tid < 32) {
        atomicAdd(&g_stats[tid],      (double)bss[tid]);
        atomicAdd(&g_stats[32 + tid], (double)bsq[tid]);
    }
}

// ---------------- k2: BN1+ReLU + conv2 + stats2 (2ch x 2pt per thread) ------
// 1024 blocks x 256 threads; tile 256 points. Thread owns channels (c, c+16),
// c = tid&15, and processes 2 points per iteration -> 4 independent fma chains.
__global__ __launch_bounds__(256) void k2_kernel(
    const float* __restrict__ w2, const float* __restrict__ b2,
    const float* __restrict__ gam, const float* __restrict__ bet)
{
    __shared__ float zp[256 * 32];      // [p][k] BN1+ReLU, 32 KB
    __shared__ float sa[32], sc[32];
    __shared__ float bss[32], bsq[32];
    int tid = threadIdx.x;
    if (tid < 32) {
        double m = g_stats[tid] * INVP;
        double v = g_stats[32 + tid] * INVP - m * m;
        double a = (double)gam[tid] / sqrt(v + EPSD);
        sa[tid] = (float)a;
        sc[tid] = (float)((double)bet[tid] - m * a);
        bss[tid] = 0.f; bsq[tid] = 0.f;
    }
    __syncthreads();

    int p0 = blockIdx.x * 256;
    const float4* y4 = (const float4*)(g_y1 + (size_t)p0 * 32);
    float4* z4 = (float4*)zp;
    #pragma unroll
    for (int it = 0; it < 8; it++) {
        int lf = it * 256 + tid;                  // [0, 2048)
        int c0 = (lf & 7) * 4;
        float4 v = y4[lf];
        v.x = fmaxf(fmaf(sa[c0 + 0], v.x, sc[c0 + 0]), 0.f);
        v.y = fmaxf(fmaf(sa[c0 + 1], v.y, sc[c0 + 1]), 0.f);
        v.z = fmaxf(fmaf(sa[c0 + 2], v.z, sc[c0 + 2]), 0.f);
        v.w = fmaxf(fmaf(sa[c0 + 3], v.w, sc[c0 + 3]), 0.f);
        z4[lf] = v;
    }

    int c  = tid & 15;                            // channels c, c+16
    int pg = tid >> 4;                            // 16 groups x 16 points
    unsigned long long wA[16], wB[16];
    #pragma unroll
    for (int k = 0; k < 16; k++) {
        wA[k] = pack2(__ldg(w2 + c * 32 + 2 * k),        __ldg(w2 + c * 32 + 2 * k + 1));
        wB[k] = pack2(__ldg(w2 + (c + 16) * 32 + 2 * k), __ldg(w2 + (c + 16) * 32 + 2 * k + 1));
    }
    float biasA = b2[c], biasB = b2[c + 16];
    __syncthreads();

    float ss0 = 0.f, sq0 = 0.f, ss1 = 0.f, sq1 = 0.f;
    #pragma unroll 1
    for (int t = 0; t < 8; t++) {
        int pA = pg * 16 + 2 * t;
        const ulonglong2* rA = (const ulonglong2*)(zp + pA * 32);
        const ulonglong2* rB = (const ulonglong2*)(zp + (pA + 1) * 32);
        unsigned long long aCA = 0, aDA = 0, aCB = 0, aDB = 0;
        #pragma unroll
        for (int k = 0; k < 8; k++) {
            ulonglong2 lA = rA[k];
            ulonglong2 lB = rB[k];
            fma2(aCA, wA[2 * k],     lA.x);
            fma2(aDA, wB[2 * k],     lA.x);
            fma2(aCB, wA[2 * k],     lB.x);
            fma2(aDB, wB[2 * k],     lB.x);
            fma2(aCA, wA[2 * k + 1], lA.y);
            fma2(aDA, wB[2 * k + 1], lA.y);
            fma2(aCB, wA[2 * k + 1], lB.y);
            fma2(aDB, wB[2 * k + 1], lB.y);
        }
        float2 uCA = unpack2(aCA), uDA = unpack2(aDA);
        float2 uCB = unpack2(aCB), uDB = unpack2(aDB);
        float yCA = uCA.x + uCA.y + biasA;
        float yDA = uDA.x + uDA.y + biasB;
        float yCB = uCB.x + uCB.y + biasA;
        float yDB = uDB.x + uDB.y + biasB;
        size_t oA = (size_t)(p0 + pA) * 32;
        g_y2[oA + c]           = yCA;
        g_y2[oA + c + 16]      = yDA;
        g_y2[oA + 32 + c]      = yCB;
        g_y2[oA + 32 + c + 16] = yDB;
        ss0 += yCA + yCB; sq0 = fmaf(yCA, yCA, fmaf(yCB, yCB, sq0));
        ss1 += yDA + yDB; sq1 = fmaf(yDA, yDA, fmaf(yDB, yDB, sq1));
    }
    atomicAdd(&bss[c], ss0);      atomicAdd(&bsq[c], sq0);
    atomicAdd(&bss[c + 16], ss1); atomicAdd(&bsq[c + 16], sq1);
    __syncthreads();
    if (tid < 32) {
        atomicAdd(&g_stats[64 + tid], (double)bss[tid]);
        atomicAdd(&g_stats[96 + tid], (double)bsq[tid]);
    }
}

// ---------------- k3: BN2+ReLU + conv3 (32->64) + stats3 (2ch x 2pt) --------
// 1024 blocks x 256 threads; tile 256 points. Thread owns (c, c+32), c=tid&31.
__global__ __launch_bounds__(256) void k3_kernel(
    const float* __restrict__ w3, const float* __restrict__ b3,
    const float* __restrict__ gam, const float* __restrict__ bet)
{
    __shared__ float zp[256 * 32];      // 32 KB
    __shared__ float sa[32], sc[32];
    __shared__ float bss[64], bsq[64];
    int tid = threadIdx.x;
    if (tid < 32) {
        double m = g_stats[64 + tid] * INVP;
        double v = g_stats[96 + tid] * INVP - m * m;
        double a = (double)gam[tid] / sqrt(v + EPSD);
        sa[tid] = (float)a;
        sc[tid] = (float)((double)bet[tid] - m * a);
    }
    if (tid < 64) { bss[tid] = 0.f; bsq[tid] = 0.f; }
    __syncthreads();

    int p0 = blockIdx.x * 256;
    const float4* y4 = (const float4*)(g_y2 + (size_t)p0 * 32);
    float4* z4 = (float4*)zp;
    #pragma unroll
    for (int it = 0; it < 8; it++) {
        int lf = it * 256 + tid;
        int c0 = (lf & 7) * 4;
        float4 v = y4[lf];
        v.x = fmaxf(fmaf(sa[c0 + 0], v.x, sc[c0 + 0]), 0.f);
        v.y = fmaxf(fmaf(sa[c0 + 1], v.y, sc[c0 + 1]), 0.f);
        v.z = fmaxf(fmaf(sa[c0 + 2], v.z, sc[c0 + 2]), 0.f);
        v.w = fmaxf(fmaf(sa[c0 + 3], v.w, sc[c0 + 3]), 0.f);
        z4[lf] = v;
    }

    int c  = tid & 31;                            // channels c, c+32
    int pg = tid >> 5;                            // 8 groups x 32 points
    unsigned long long wA[16], wB[16];
    #pragma unroll
    for (int k = 0; k < 16; k++) {
        wA[k] = pack2(__ldg(w3 + c * 32 + 2 * k),        __ldg(w3 + c * 32 + 2 * k + 1));
        wB[k] = pack2(__ldg(w3 + (c + 32) * 32 + 2 * k), __ldg(w3 + (c + 32) * 32 + 2 * k + 1));
    }
    float biasA = b3[c], biasB = b3[c + 32];
    __syncthreads();

    float ss0 = 0.f, sq0 = 0.f, ss1 = 0.f, sq1 = 0.f;
    #pragma unroll 1
    for (int t = 0; t < 16; t++) {
        int pA = pg * 32 + 2 * t;
        const ulonglong2* rA = (const ulonglong2*)(zp + pA * 32);
        const ulonglong2* rB = (const ulonglong2*)(zp + (pA + 1) * 32);
        unsigned long long aCA = 0, aDA = 0, aCB = 0, aDB = 0;
        #pragma unroll
        for (int k = 0; k < 8; k++) {
            ulonglong2 lA = rA[k];
            ulonglong2 lB = rB[k];
            fma2(aCA, wA[2 * k],     lA.x);
            fma2(aDA, wB[2 * k],     lA.x);
            fma2(aCB, wA[2 * k],     lB.x);
            fma2(aDB, wB[2 * k],     lB.x);
            fma2(aCA, wA[2 * k + 1], lA.y);
            fma2(aDA, wB[2 * k + 1], lA.y);
            fma2(aCB, wA[2 * k + 1], lB.y);
            fma2(aDB, wB[2 * k + 1], lB.y);
        }
        float2 uCA = unpack2(aCA), uDA = unpack2(aDA);
        float2 uCB = unpack2(aCB), uDB = unpack2(aDB);
        float yCA = uCA.x + uCA.y + biasA;
        float yDA = uDA.x + uDA.y + biasB;
        float yCB = uCB.x + uCB.y + biasA;
        float yDB = uDB.x + uDB.y + biasB;
        size_t oA = (size_t)(p0 + pA) * 64;
        g_y3[oA + c]           = yCA;
        g_y3[oA + c + 32]      = yDA;
        g_y3[oA + 64 + c]      = yCB;
        g_y3[oA + 64 + c + 32] = yDB;
        ss0 += yCA + yCB; sq0 = fmaf(yCA, yCA, fmaf(yCB, yCB, sq0));
        ss1 += yDA + yDB; sq1 = fmaf(yDA, yDA, fmaf(yDB, yDB, sq1));
    }
    atomicAdd(&bss[c], ss0);      atomicAdd(&bsq[c], sq0);
    atomicAdd(&bss[c + 32], ss1); atomicAdd(&bsq[c + 32], sq1);
    __syncthreads();
    if (tid < 64) {
        atomicAdd(&g_stats[128 + tid], (double)bss[tid]);
        atomicAdd(&g_stats[192 + tid], (double)bsq[tid]);
    }
}

// ---------------- k4: BN3+ReLU + valid mask + transpose to [B,64,S,K] ------
// Vectorized: float4 reads, float4 writes; 64-point x 64-ch tile per block.
__global__ __launch_bounds__(256) void k4_kernel(
    float* __restrict__ out,
    const float* __restrict__ gam, const float* __restrict__ bet)
{
    __shared__ float tile[64 * 65];
    __shared__ float sa[64], sc[64];
    int tid = threadIdx.x;
    if (tid < 64) {
        double m = g_stats[128 + tid] * INVP;
        double v = g_stats[192 + tid] * INVP - m * m;
        double a = (double)gam[tid] / sqrt(v + EPSD);
        sa[tid] = (float)a;
        sc[tid] = (float)((double)bet[tid] - m * a);
    }
    __syncthreads();

    int pt0 = blockIdx.x * 64;
    int b   = pt0 >> 16;
    int w0  = pt0 & 65535;
    const float4* src4 = (const float4*)(g_y3 + (size_t)pt0 * 64);
    #pragma unroll
    for (int it = 0; it < 4; it++) {
        int lf = it * 256 + tid;                 // [0, 1024)
        int p = lf >> 4, c0 = (lf & 15) * 4;
        float4 v = src4[lf];
        float vm = (float)g_valid[(pt0 + p) >> 5];
        tile[p * 65 + c0 + 0] = fmaxf(fmaf(sa[c0 + 0], v.x, sc[c0 + 0]), 0.f) * vm;
        tile[p * 65 + c0 + 1] = fmaxf(fmaf(sa[c0 + 1], v.y, sc[c0 + 1]), 0.f) * vm;
        tile[p * 65 + c0 + 2] = fmaxf(fmaf(sa[c0 + 2], v.z, sc[c0 + 2]), 0.f) * vm;
        tile[p * 65 + c0 + 3] = fmaxf(fmaf(sa[c0 + 3], v.w, sc[c0 + 3]), 0.f) * vm;
    }
    __syncthreads();
    float* ob = out + (size_t)b * 64 * 65536 + w0;
    #pragma unroll
    for (int it = 0; it < 4; it++) {
        int lf = it * 256 + tid;
        int c = lf >> 4, pq = (lf & 15) * 4;
        float4 v = make_float4(tile[(pq + 0) * 65 + c], tile[(pq + 1) * 65 + c],
                               tile[(pq + 2) * 65 + c], tile[(pq + 3) * 65 + c]);
        *(float4*)(ob + (size_t)c * 65536 + pq) = v;
    }
}

// ---------------- launch ---------------------------------------------------
extern "C" void kernel_launch(void* const* d_in, const int* in_sizes, int n_in,
                              void* d_out, int out_size)
{
    const float* pc   = (const float*)d_in[0];
    const float* feat = (const float*)d_in[1];
    const float* npc  = (const float*)d_in[2];
    const float* w1   = (const float*)d_in[3];
    const float* b1   = (const float*)d_in[4];
    const float* g1   = (const float*)d_in[5];
    const float* be1  = (const float*)d_in[6];
    const float* w2   = (const float*)d_in[7];
    const float* b2   = (const float*)d_in[8];
    const float* g2   = (const float*)d_in[9];
    const float* be2  = (const float*)d_in[10];
    const float* w3   = (const float*)d_in[11];
    const float* b3   = (const float*)d_in[12];
    const float* g3   = (const float*)d_in[13];
    const float* be3  = (const float*)d_in[14];
    float* out = (float*)d_out;

    cudaFuncSetAttribute(k1_kernel, cudaFuncAttributeMaxDynamicSharedMemorySize,
                         3 * NP * sizeof(float));

    prep_kernel<<<512, 256>>>(feat);
    k1_kernel<<<256, 256, 3 * NP * sizeof(float)>>>(pc, npc, w1, b1);
    k2_kernel<<<1024, 256>>>(w2, b2, g1, be1);
    k3_kernel<<<1024, 256>>>(w3, b3, g2, be2);
    k4_kernel<<<4096, 256>>>(out, g3, be3);
}

// round 10
// speedup vs baseline: 1.4803x; 1.4390x over previous
#include <cuda_runtime.h>

#define BQ 4
#define NP 8192
#define SQ 2048
#define CF 16
#define KN 32
constexpr int    P    = BQ * SQ * KN;        // 262144 points
constexpr float  R2   = 0.25f;
constexpr double EPSD = 1e-5;
constexpr double INVP = 1.0 / (double)P;

// ---------------- scratch ----------------
__device__ int    g_valid[BQ * SQ];
__device__ float  g_featT[(size_t)BQ * NP * CF];   // [b][j][c] point-major
__device__ float  g_y1[(size_t)P * 32];
__device__ float  g_y2[(size_t)P * 32];
__device__ float  g_y3[(size_t)P * 64];
// [0:32)sum1 [32:64)sq1 [64:96)sum2 [96:128)sq2 [128:192)sum3 [192:256)sq3
__device__ double g_stats[256];

// ---------------- f32x2 helpers ----------------
__device__ __forceinline__ unsigned long long pack2(float a, float b) {
    unsigned long long r;
    asm("mov.b64 %0, {%1, %2};" : "=l"(r) : "f"(a), "f"(b));
    return r;
}
__device__ __forceinline__ unsigned long long dup2(float a) {
    unsigned long long r;
    asm("mov.b64 %0, {%1, %1};" : "=l"(r) : "f"(a));
    return r;
}
__device__ __forceinline__ void fma2(unsigned long long& d,
                                     unsigned long long a, unsigned long long b) {
    asm("fma.rn.f32x2 %0, %1, %2, %0;" : "+l"(d) : "l"(a), "l"(b));
}
__device__ __forceinline__ float2 unpack2(unsigned long long v) {
    float lo, hi;
    asm("mov.b64 {%0, %1}, %2;" : "=f"(lo), "=f"(hi) : "l"(v));
    return make_float2(lo, hi);
}

// Warp transpose-fold (used only in k1).
__device__ __forceinline__ void warp_fold(float* s, float* t, int lane,
                                          float& osum, float& osq) {
    #pragma unroll
    for (int st = 0; st < 5; st++) {
        int wbit = 1 << st;
        bool hi = (lane & wbit) != 0;
        #pragma unroll
        for (int k = 0; k < (16 >> st); k++) {
            float slo = s[2 * k], shi = s[2 * k + 1];
            float ssend = hi ? slo : shi;
            float skeep = hi ? shi : slo;
            s[k] = skeep + __shfl_xor_sync(0xffffffffu, ssend, wbit);
            float tlo = t[2 * k], thi = t[2 * k + 1];
            float tsend = hi ? tlo : thi;
            float tkeep = hi ? thi : tlo;
            t[k] = tkeep + __shfl_xor_sync(0xffffffffu, tsend, wbit);
        }
    }
    osum = s[0]; osq = t[0];
}

// ---------------- prep: zero stats + transpose feat to point-major ----------
__global__ __launch_bounds__(256) void prep_kernel(const float* __restrict__ feat) {
    __shared__ float tile[16][65];
    int tid = threadIdx.x;
    if (blockIdx.x == 0) g_stats[tid] = 0.0;
    int b  = blockIdx.x >> 7;
    int j0 = (blockIdx.x & 127) * 64;
    const float* f = feat + (size_t)b * CF * NP;
    #pragma unroll
    for (int i = tid; i < 1024; i += 256) {
        int c = i >> 6, jj = i & 63;
        tile[c][jj] = f[(size_t)c * NP + j0 + jj];
    }
    __syncthreads();
    float* o = g_featT + ((size_t)b * NP + j0) * CF;
    #pragma unroll
    for (int i = tid; i < 1024; i += 256) {
        int jj = i >> 4, c = i & 15;
        o[i] = tile[c][jj];
    }
}

// ---------------- k1: ball query + gather + conv1 + stats1 -----------------
__global__ __launch_bounds__(256) void k1_kernel(
    const float* __restrict__ pc, const float* __restrict__ newpc,
    const float* __restrict__ w1, const float* __restrict__ b1)
{
    extern __shared__ float spc[];                 // 3*NP floats (96 KB)
    __shared__ unsigned long long swp[19 * 16];
    __shared__ unsigned long long sbp[16];
    __shared__ float bss[32], bsq[32];
    __shared__ int   sIdx[8][KN];

    int tid = threadIdx.x, lane = tid & 31, w = tid >> 5;
    int qb = blockIdx.x * 32;
    int b  = qb >> 11;

    const float4* src = (const float4*)(pc + (size_t)b * 3 * NP);
    float4* d4 = (float4*)spc;
    #pragma unroll 4
    for (int i = tid; i < (3 * NP) / 4; i += 256) d4[i] = src[i];
    for (int i = tid; i < 304; i += 256) {
        int ci = i >> 4, c2 = i & 15;
        swp[i] = pack2(w1[(2 * c2) * 19 + ci], w1[(2 * c2 + 1) * 19 + ci]);
    }
    if (tid < 16) sbp[tid] = pack2(b1[2 * tid], b1[2 * tid + 1]);
    if (tid < 32) { bss[tid] = 0.f; bsq[tid] = 0.f; }
    __syncthreads();

    #pragma unroll 1
    for (int qi = 0; qi < 4; qi++) {
        int q  = qb + w * 4 + qi;
        int sl = q & (SQ - 1);
        const float* np = newpc + (size_t)b * 3 * SQ + sl;
        float qx = np[0], qy = np[SQ], qz = np[2 * SQ];

        int count = 0, firstidx = 0;
        for (int j0 = 0; j0 < NP; j0 += 64) {
            int ja = j0 + lane, jb = ja + 32;
            float ax = spc[ja] - qx, ay = spc[NP + ja] - qy, az = spc[2 * NP + ja] - qz;
            float bx = spc[jb] - qx, by = spc[NP + jb] - qy, bz = spc[2 * NP + jb] - qz;
            bool ina = fmaf(ax, ax, fmaf(ay, ay, az * az)) < R2;
            bool inb = fmaf(bx, bx, fmaf(by, by, bz * bz)) < R2;
            unsigned ma = __ballot_sync(0xffffffffu, ina);
            unsigned mb = __ballot_sync(0xffffffffu, inb);
            if (ma | mb) {
                if (count == 0)
                    firstidx = ma ? (j0 + __ffs((int)ma) - 1)
                                  : (j0 + 32 + __ffs((int)mb) - 1);
                if (ina) {
                    int slot = count + __popc(ma & ((1u << lane) - 1u));
                    if (slot < KN) sIdx[w][slot] = ja;
                }
                int ca = count + __popc(ma);
                if (inb) {
                    int slot = ca + __popc(mb & ((1u << lane) - 1u));
                    if (slot < KN) sIdx[w][slot] = jb;
                }
                count = ca + __popc(mb);
                if (count >= KN) break;
            }
        }
        if (lane >= count) sIdx[w][lane] = firstidx;
        if (lane == 0) g_valid[q] = (count > 0) ? 1 : 0;
        __syncwarp();
        int j = sIdx[w][lane];
        __syncwarp();

        float x[19];
        x[0] = spc[j] - qx; x[1] = spc[NP + j] - qy; x[2] = spc[2 * NP + j] - qz;
        const float4* ft = (const float4*)(g_featT + ((size_t)b * NP + j) * CF);
        float4 f;
        f = ft[0]; x[3]  = f.x; x[4]  = f.y; x[5]  = f.z; x[6]  = f.w;
        f = ft[1]; x[7]  = f.x; x[8]  = f.y; x[9]  = f.z; x[10] = f.w;
        f = ft[2]; x[11] = f.x; x[12] = f.y; x[13] = f.z; x[14] = f.w;
        f = ft[3]; x[15] = f.x; x[16] = f.y; x[17] = f.z; x[18] = f.w;

        unsigned long long acc[16];
        #pragma unroll
        for (int c2 = 0; c2 < 16; c2++) acc[c2] = sbp[c2];
        #pragma unroll
        for (int i = 0; i < 19; i++) {
            unsigned long long xx = dup2(x[i]);
            const ulonglong2* wp = (const ulonglong2*)(swp + i * 16);
            #pragma unroll
            for (int c4 = 0; c4 < 8; c4++) {
                ulonglong2 wv = wp[c4];
                fma2(acc[2 * c4],     wv.x, xx);
                fma2(acc[2 * c4 + 1], wv.y, xx);
            }
        }
        float y[32], yq[32];
        #pragma unroll
        for (int c2 = 0; c2 < 16; c2++) {
            float2 u = unpack2(acc[c2]);
            y[2 * c2] = u.x; y[2 * c2 + 1] = u.y;
        }
        float4* dst = (float4*)(g_y1 + ((size_t)q * 32 + lane) * 32);
        #pragma unroll
        for (int c4 = 0; c4 < 8; c4++)
            dst[c4] = make_float4(y[4 * c4], y[4 * c4 + 1], y[4 * c4 + 2], y[4 * c4 + 3]);
        #pragma unroll
        for (int c = 0; c < 32; c++) yq[c] = y[c] * y[c];
        float osum, osq;
        warp_fold(y, yq, lane, osum, osq);
        atomicAdd(&bss[lane], osum);
        atomicAdd(&bsq[lane], osq);
    }
    __syncthreads();
    if (tid < 32) {
        atomicAdd(&g_stats[tid],      (double)bss[tid]);
        atomicAdd(&g_stats[32 + tid], (double)bsq[tid]);
    }
}

// ---------------- k2: BN1+ReLU + conv2 + stats2 (2ch x 2pt per thread) ------
// Weights staged k-major in smem: swt[k*32 + c] -> conflict-free lane reads.
__global__ __launch_bounds__(256) void k2_kernel(
    const float* __restrict__ w2, const float* __restrict__ b2,
    const float* __restrict__ gam, const float* __restrict__ bet)
{
    __shared__ float zp[256 * 32];      // [p][k] BN1+ReLU, 32 KB
    __shared__ float swt[1024];         // [k][c] transposed weights
    __shared__ float sa[32], sc[32];
    __shared__ float bss[32], bsq[32];
    int tid = threadIdx.x;
    if (tid < 32) {
        double m = g_stats[tid] * INVP;
        double v = g_stats[32 + tid] * INVP - m * m;
        double a = (double)gam[tid] / sqrt(v + EPSD);
        sa[tid] = (float)a;
        sc[tid] = (float)((double)bet[tid] - m * a);
        bss[tid] = 0.f; bsq[tid] = 0.f;
    }
    #pragma unroll
    for (int i = tid; i < 1024; i += 256) {
        int co = i >> 5, k = i & 31;     // w2[co][k], coalesced load
        swt[k * 32 + co] = w2[i];
    }
    __syncthreads();

    int p0 = blockIdx.x * 256;
    const float4* y4 = (const float4*)(g_y1 + (size_t)p0 * 32);
    float4* z4 = (float4*)zp;
    #pragma unroll
    for (int it = 0; it < 8; it++) {
        int lf = it * 256 + tid;                  // [0, 2048)
        int c0 = (lf & 7) * 4;
        float4 v = y4[lf];
        v.x = fmaxf(fmaf(sa[c0 + 0], v.x, sc[c0 + 0]), 0.f);
        v.y = fmaxf(fmaf(sa[c0 + 1], v.y, sc[c0 + 1]), 0.f);
        v.z = fmaxf(fmaf(sa[c0 + 2], v.z, sc[c0 + 2]), 0.f);
        v.w = fmaxf(fmaf(sa[c0 + 3], v.w, sc[c0 + 3]), 0.f);
        z4[lf] = v;
    }
    __syncthreads();

    int c  = tid & 15;                            // channels c, c+16
    int pg = tid >> 4;                            // 16 groups x 16 points
    unsigned long long wA[16], wB[16];
    #pragma unroll
    for (int k = 0; k < 16; k++) {                // conflict-free LDS.32
        wA[k] = pack2(swt[(2 * k) * 32 + c],      swt[(2 * k + 1) * 32 + c]);
        wB[k] = pack2(swt[(2 * k) * 32 + c + 16], swt[(2 * k + 1) * 32 + c + 16]);
    }
    float biasA = b2[c], biasB = b2[c + 16];

    float ss0 = 0.f, sq0 = 0.f, ss1 = 0.f, sq1 = 0.f;
    #pragma unroll 1
    for (int t = 0; t < 8; t++) {
        int pA = pg * 16 + 2 * t;
        const ulonglong2* rA = (const ulonglong2*)(zp + pA * 32);
        const ulonglong2* rB = (const ulonglong2*)(zp + (pA + 1) * 32);
        unsigned long long aCA = 0, aDA = 0, aCB = 0, aDB = 0;
        #pragma unroll
        for (int k = 0; k < 8; k++) {
            ulonglong2 lA = rA[k];
            ulonglong2 lB = rB[k];
            fma2(aCA, wA[2 * k],     lA.x);
            fma2(aDA, wB[2 * k],     lA.x);
            fma2(aCB, wA[2 * k],     lB.x);
            fma2(aDB, wB[2 * k],     lB.x);
            fma2(aCA, wA[2 * k + 1], lA.y);
            fma2(aDA, wB[2 * k + 1], lA.y);
            fma2(aCB, wA[2 * k + 1], lB.y);
            fma2(aDB, wB[2 * k + 1], lB.y);
        }
        float2 uCA = unpack2(aCA), uDA = unpack2(aDA);
        float2 uCB = unpack2(aCB), uDB = unpack2(aDB);
        float yCA = uCA.x + uCA.y + biasA;
        float yDA = uDA.x + uDA.y + biasB;
        float yCB = uCB.x + uCB.y + biasA;
        float yDB = uDB.x + uDB.y + biasB;
        size_t oA = (size_t)(p0 + pA) * 32;
        g_y2[oA + c]           = yCA;
        g_y2[oA + c + 16]      = yDA;
        g_y2[oA + 32 + c]      = yCB;
        g_y2[oA + 32 + c + 16] = yDB;
        ss0 += yCA + yCB; sq0 = fmaf(yCA, yCA, fmaf(yCB, yCB, sq0));
        ss1 += yDA + yDB; sq1 = fmaf(yDA, yDA, fmaf(yDB, yDB, sq1));
    }
    atomicAdd(&bss[c], ss0);      atomicAdd(&bsq[c], sq0);
    atomicAdd(&bss[c + 16], ss1); atomicAdd(&bsq[c + 16], sq1);
    __syncthreads();
    if (tid < 32) {
        atomicAdd(&g_stats[64 + tid], (double)bss[tid]);
        atomicAdd(&g_stats[96 + tid], (double)bsq[tid]);
    }
}

// ---------------- k3: BN2+ReLU + conv3 (32->64) + stats3 (2ch x 2pt) --------
// Weights staged k-major in smem: swt[k*64 + c] -> conflict-free lane reads.
__global__ __launch_bounds__(256) void k3_kernel(
    const float* __restrict__ w3, const float* __restrict__ b3,
    const float* __restrict__ gam, const float* __restrict__ bet)
{
    __shared__ float zp[256 * 32];      // 32 KB
    __shared__ float swt[2048];         // [k][c] transposed weights
    __shared__ float sa[32], sc[32];
    __shared__ float bss[64], bsq[64];
    int tid = threadIdx.x;
    if (tid < 32) {
        double m = g_stats[64 + tid] * INVP;
        double v = g_stats[96 + tid] * INVP - m * m;
        double a = (double)gam[tid] / sqrt(v + EPSD);
        sa[tid] = (float)a;
        sc[tid] = (float)((double)bet[tid] - m * a);
    }
    if (tid < 64) { bss[tid] = 0.f; bsq[tid] = 0.f; }
    #pragma unroll
    for (int i = tid; i < 2048; i += 256) {
        int co = i >> 5, k = i & 31;     // w3[co][k], coalesced load
        swt[k * 64 + co] = w3[i];
    }
    __syncthreads();

    int p0 = blockIdx.x * 256;
    const float4* y4 = (const float4*)(g_y2 + (size_t)p0 * 32);
    float4* z4 = (float4*)zp;
    #pragma unroll
    for (int it = 0; it < 8; it++) {
        int lf = it * 256 + tid;
        int c0 = (lf & 7) * 4;
        float4 v = y4[lf];
        v.x = fmaxf(fmaf(sa[c0 + 0], v.x, sc[c0 + 0]), 0.f);
        v.y = fmaxf(fmaf(sa[c0 + 1], v.y, sc[c0 + 1]), 0.f);
        v.z = fmaxf(fmaf(sa[c0 + 2], v.z, sc[c0 + 2]), 0.f);
        v.w = fmaxf(fmaf(sa[c0 + 3], v.w, sc[c0 + 3]), 0.f);
        z4[lf] = v;
    }
    __syncthreads();

    int c  = tid & 31;                            // channels c, c+32
    int pg = tid >> 5;                            // 8 groups x 32 points
    unsigned long long wA[16], wB[16];
    #pragma unroll
    for (int k = 0; k < 16; k++) {                // conflict-free LDS.32
        wA[k] = pack2(swt[(2 * k) * 64 + c],      swt[(2 * k + 1) * 64 + c]);
        wB[k] = pack2(swt[(2 * k) * 64 + c + 32], swt[(2 * k + 1) * 64 + c + 32]);
    }
    float biasA = b3[c], biasB = b3[c + 32];

    float ss0 = 0.f, sq0 = 0.f, ss1 = 0.f, sq1 = 0.f;
    #pragma unroll 1
    for (int t = 0; t < 16; t++) {
        int pA = pg * 32 + 2 * t;
        const ulonglong2* rA = (const ulonglong2*)(zp + pA * 32);
        const ulonglong2* rB = (const ulonglong2*)(zp + (pA + 1) * 32);
        unsigned long long aCA = 0, aDA = 0, aCB = 0, aDB = 0;
        #pragma unroll
        for (int k = 0; k < 8; k++) {
            ulonglong2 lA = rA[k];
            ulonglong2 lB = rB[k];
            fma2(aCA, wA[2 * k],     lA.x);
            fma2(aDA, wB[2 * k],     lA.x);
            fma2(aCB, wA[2 * k],     lB.x);
            fma2(aDB, wB[2 * k],     lB.x);
            fma2(aCA, wA[2 * k + 1], lA.y);
            fma2(aDA, wB[2 * k + 1], lA.y);
            fma2(aCB, wA[2 * k + 1], lB.y);
            fma2(aDB, wB[2 * k + 1], lB.y);
        }
        float2 uCA = unpack2(aCA), uDA = unpack2(aDA);
        float2 uCB = unpack2(aCB), uDB = unpack2(aDB);
        float yCA = uCA.x + uCA.y + biasA;
        float yDA = uDA.x + uDA.y + biasB;
        float yCB = uCB.x + uCB.y + biasA;
        float yDB = uDB.x + uDB.y + biasB;
        size_t oA = (size_t)(p0 + pA) * 64;
        g_y3[oA + c]           = yCA;
        g_y3[oA + c + 32]      = yDA;
        g_y3[oA + 64 + c]      = yCB;
        g_y3[oA + 64 + c + 32] = yDB;
        ss0 += yCA + yCB; sq0 = fmaf(yCA, yCA, fmaf(yCB, yCB, sq0));
        ss1 += yDA + yDB; sq1 = fmaf(yDA, yDA, fmaf(yDB, yDB, sq1));
    }
    atomicAdd(&bss[c], ss0);      atomicAdd(&bsq[c], sq0);
    atomicAdd(&bss[c + 32], ss1); atomicAdd(&bsq[c + 32], sq1);
    __syncthreads();
    if (tid < 64) {
        atomicAdd(&g_stats[128 + tid], (double)bss[tid]);
        atomicAdd(&g_stats[192 + tid], (double)bsq[tid]);
    }
}

// ---------------- k4: BN3+ReLU + valid mask + transpose to [B,64,S,K] ------
__global__ __launch_bounds__(256) void k4_kernel(
    float* __restrict__ out,
    const float* __restrict__ gam, const float* __restrict__ bet)
{
    __shared__ float tile[64 * 65];
    __shared__ float sa[64], sc[64];
    int tid = threadIdx.x;
    if (tid < 64) {
        double m = g_stats[128 + tid] * INVP;
        double v = g_stats[192 + tid] * INVP - m * m;
        double a = (double)gam[tid] / sqrt(v + EPSD);
        sa[tid] = (float)a;
        sc[tid] = (float)((double)bet[tid] - m * a);
    }
    __syncthreads();

    int pt0 = blockIdx.x * 64;
    int b   = pt0 >> 16;
    int w0  = pt0 & 65535;
    const float4* src4 = (const float4*)(g_y3 + (size_t)pt0 * 64);
    #pragma unroll
    for (int it = 0; it < 4; it++) {
        int lf = it * 256 + tid;                 // [0, 1024)
        int p = lf >> 4, c0 = (lf & 15) * 4;
        float4 v = src4[lf];
        float vm = (float)g_valid[(pt0 + p) >> 5];
        tile[p * 65 + c0 + 0] = fmaxf(fmaf(sa[c0 + 0], v.x, sc[c0 + 0]), 0.f) * vm;
        tile[p * 65 + c0 + 1] = fmaxf(fmaf(sa[c0 + 1], v.y, sc[c0 + 1]), 0.f) * vm;
        tile[p * 65 + c0 + 2] = fmaxf(fmaf(sa[c0 + 2], v.z, sc[c0 + 2]), 0.f) * vm;
        tile[p * 65 + c0 + 3] = fmaxf(fmaf(sa[c0 + 3], v.w, sc[c0 + 3]), 0.f) * vm;
    }
    __syncthreads();
    float* ob = out + (size_t)b * 64 * 65536 + w0;
    #pragma unroll
    for (int it = 0; it < 4; it++) {
        int lf = it * 256 + tid;
        int c = lf >> 4, pq = (lf & 15) * 4;
        float4 v = make_float4(tile[(pq + 0) * 65 + c], tile[(pq + 1) * 65 + c],
                               tile[(pq + 2) * 65 + c], tile[(pq + 3) * 65 + c]);
        *(float4*)(ob + (size_t)c * 65536 + pq) = v;
    }
}

// ---------------- launch ---------------------------------------------------
extern "C" void kernel_launch(void* const* d_in, const int* in_sizes, int n_in,
                              void* d_out, int out_size)
{
    const float* pc   = (const float*)d_in[0];
    const float* feat = (const float*)d_in[1];
    const float* npc  = (const float*)d_in[2];
    const float* w1   = (const float*)d_in[3];
    const float* b1   = (const float*)d_in[4];
    const float* g1   = (const float*)d_in[5];
    const float* be1  = (const float*)d_in[6];
    const float* w2   = (const float*)d_in[7];
    const float* b2   = (const float*)d_in[8];
    const float* g2   = (const float*)d_in[9];
    const float* be2  = (const float*)d_in[10];
    const float* w3   = (const float*)d_in[11];
    const float* b3   = (const float*)d_in[12];
    const float* g3   = (const float*)d_in[13];
    const float* be3  = (const float*)d_in[14];
    float* out = (float*)d_out;

    cudaFuncSetAttribute(k1_kernel, cudaFuncAttributeMaxDynamicSharedMemorySize,
                         3 * NP * sizeof(float));

    prep_kernel<<<512, 256>>>(feat);
    k1_kernel<<<256, 256, 3 * NP * sizeof(float)>>>(pc, npc, w1, b1);
    k2_kernel<<<1024, 256>>>(w2, b2, g1, be1);
    k3_kernel<<<1024, 256>>>(w3, b3, g2, be2);
    k4_kernel<<<4096, 256>>>(out, g3, be3);
}

// round 11
// speedup vs baseline: 1.5464x; 1.0446x over previous
#include <cuda_runtime.h>

#define BQ 4
#define NP 8192
#define SQ 2048
#define CF 16
#define KN 32
constexpr int    P    = BQ * SQ * KN;        // 262144 points
constexpr float  R2   = 0.25f;
constexpr double EPSD = 1e-5;
constexpr double INVP = 1.0 / (double)P;

// ---------------- scratch ----------------
__device__ int    g_valid[BQ * SQ];
__device__ float  g_featT[(size_t)BQ * NP * CF];   // [b][j][c] point-major
__device__ float  g_y1[(size_t)P * 32];
__device__ float  g_y2[(size_t)P * 32];
__device__ float  g_y3[(size_t)P * 64];
// [0:32)sum1 [32:64)sq1 [64:96)sum2 [96:128)sq2 [128:192)sum3 [192:256)sq3
__device__ double g_stats[256];

// ---------------- f32x2 helpers ----------------
__device__ __forceinline__ unsigned long long pack2(float a, float b) {
    unsigned long long r;
    asm("mov.b64 %0, {%1, %2};" : "=l"(r) : "f"(a), "f"(b));
    return r;
}
__device__ __forceinline__ unsigned long long dup2(float a) {
    unsigned long long r;
    asm("mov.b64 %0, {%1, %1};" : "=l"(r) : "f"(a));
    return r;
}
__device__ __forceinline__ void fma2(unsigned long long& d,
                                     unsigned long long a, unsigned long long b) {
    asm("fma.rn.f32x2 %0, %1, %2, %0;" : "+l"(d) : "l"(a), "l"(b));
}
__device__ __forceinline__ unsigned long long add2v(unsigned long long a,
                                                    unsigned long long b) {
    unsigned long long r;
    asm("add.rn.f32x2 %0, %1, %2;" : "=l"(r) : "l"(a), "l"(b));
    return r;
}
__device__ __forceinline__ unsigned long long mul2v(unsigned long long a,
                                                    unsigned long long b) {
    unsigned long long r;
    asm("mul.rn.f32x2 %0, %1, %2;" : "=l"(r) : "l"(a), "l"(b));
    return r;
}
__device__ __forceinline__ float2 unpack2(unsigned long long v) {
    float lo, hi;
    asm("mov.b64 {%0, %1}, %2;" : "=f"(lo), "=f"(hi) : "l"(v));
    return make_float2(lo, hi);
}

// Warp transpose-fold (used only in k1).
__device__ __forceinline__ void warp_fold(float* s, float* t, int lane,
                                          float& osum, float& osq) {
    #pragma unroll
    for (int st = 0; st < 5; st++) {
        int wbit = 1 << st;
        bool hi = (lane & wbit) != 0;
        #pragma unroll
        for (int k = 0; k < (16 >> st); k++) {
            float slo = s[2 * k], shi = s[2 * k + 1];
            float ssend = hi ? slo : shi;
            float skeep = hi ? shi : slo;
            s[k] = skeep + __shfl_xor_sync(0xffffffffu, ssend, wbit);
            float tlo = t[2 * k], thi = t[2 * k + 1];
            float tsend = hi ? tlo : thi;
            float tkeep = hi ? thi : tlo;
            t[k] = tkeep + __shfl_xor_sync(0xffffffffu, tsend, wbit);
        }
    }
    osum = s[0]; osq = t[0];
}

// ---------------- prep: zero stats + transpose feat to point-major ----------
__global__ __launch_bounds__(256) void prep_kernel(const float* __restrict__ feat) {
    __shared__ float tile[16][65];
    int tid = threadIdx.x;
    if (blockIdx.x == 0) g_stats[tid] = 0.0;
    int b  = blockIdx.x >> 7;
    int j0 = (blockIdx.x & 127) * 64;
    const float* f = feat + (size_t)b * CF * NP;
    #pragma unroll
    for (int i = tid; i < 1024; i += 256) {
        int c = i >> 6, jj = i & 63;
        tile[c][jj] = f[(size_t)c * NP + j0 + jj];
    }
    __syncthreads();
    float* o = g_featT + ((size_t)b * NP + j0) * CF;
    #pragma unroll
    for (int i = tid; i < 1024; i += 256) {
        int jj = i >> 4, c = i & 15;
        o[i] = tile[c][jj];
    }
}

// ---------------- k1: ball query + gather + conv1 + stats1 -----------------
// Scan vectorized: 4 points per lane per iteration (f32x2 packed distances),
// distance DAG kept bit-identical to scalar version (mul -> fma -> fma).
__global__ __launch_bounds__(256) void k1_kernel(
    const float* __restrict__ pc, const float* __restrict__ newpc,
    const float* __restrict__ w1, const float* __restrict__ b1)
{
    extern __shared__ float spc[];                 // 3*NP floats (96 KB)
    __shared__ unsigned long long swp[19 * 16];
    __shared__ unsigned long long sbp[16];
    __shared__ float bss[32], bsq[32];
    __shared__ int   sIdx[8][KN];

    int tid = threadIdx.x, lane = tid & 31, w = tid >> 5;
    int qb = blockIdx.x * 32;
    int b  = qb >> 11;

    const float4* src = (const float4*)(pc + (size_t)b * 3 * NP);
    float4* d4 = (float4*)spc;
    #pragma unroll 4
    for (int i = tid; i < (3 * NP) / 4; i += 256) d4[i] = src[i];
    for (int i = tid; i < 304; i += 256) {
        int ci = i >> 4, c2 = i & 15;
        swp[i] = pack2(w1[(2 * c2) * 19 + ci], w1[(2 * c2 + 1) * 19 + ci]);
    }
    if (tid < 16) sbp[tid] = pack2(b1[2 * tid], b1[2 * tid + 1]);
    if (tid < 32) { bss[tid] = 0.f; bsq[tid] = 0.f; }
    __syncthreads();

    const ulonglong2* sx2 = (const ulonglong2*)(spc);
    const ulonglong2* sy2 = (const ulonglong2*)(spc + NP);
    const ulonglong2* sz2 = (const ulonglong2*)(spc + 2 * NP);

    #pragma unroll 1
    for (int qi = 0; qi < 4; qi++) {
        int q  = qb + w * 4 + qi;
        int sl = q & (SQ - 1);
        const float* np = newpc + (size_t)b * 3 * SQ + sl;
        float qx = np[0], qy = np[SQ], qz = np[2 * SQ];
        unsigned long long nqx = dup2(-qx), nqy = dup2(-qy), nqz = dup2(-qz);

        int count = 0, firstidx = 0;
        #pragma unroll 1
        for (int j0 = 0; j0 < NP; j0 += 128) {
            int i4 = (j0 >> 2) + lane;             // each ulonglong2 = 4 floats
            ulonglong2 X = sx2[i4];
            ulonglong2 Y = sy2[i4];
            ulonglong2 Z = sz2[i4];
            unsigned long long dx0 = add2v(X.x, nqx), dx1 = add2v(X.y, nqx);
            unsigned long long dy0 = add2v(Y.x, nqy), dy1 = add2v(Y.y, nqy);
            unsigned long long dz0 = add2v(Z.x, nqz), dz1 = add2v(Z.y, nqz);
            unsigned long long t0 = mul2v(dz0, dz0), t1 = mul2v(dz1, dz1);
            fma2(t0, dy0, dy0); fma2(t1, dy1, dy1);
            fma2(t0, dx0, dx0); fma2(t1, dx1, dx1);
            float2 f0 = unpack2(t0), f1 = unpack2(t1);
            unsigned m0 = __ballot_sync(0xffffffffu, f0.x < R2);
            unsigned m1 = __ballot_sync(0xffffffffu, f0.y < R2);
            unsigned m2 = __ballot_sync(0xffffffffu, f1.x < R2);
            unsigned m3 = __ballot_sync(0xffffffffu, f1.y < R2);
            unsigned any = m0 | m1 | m2 | m3;
            if (any) {
                if (count == 0) {
                    int lm = __ffs((int)any) - 1;
                    int cm = ((m0 >> lm) & 1) ? 0 : (((m1 >> lm) & 1) ? 1
                             : (((m2 >> lm) & 1) ? 2 : 3));
                    firstidx = j0 + 4 * lm + cm;
                }
                unsigned below = (1u << lane) - 1u;
                int b0 = (m0 >> lane) & 1, b1m = (m1 >> lane) & 1;
                int b2m = (m2 >> lane) & 1, b3m = (m3 >> lane) & 1;
                int s = count + __popc(m0 & below) + __popc(m1 & below)
                              + __popc(m2 & below) + __popc(m3 & below);
                int jb4 = j0 + 4 * lane;
                if (b0 && s < KN)  sIdx[w][s] = jb4;
                s += b0;
                if (b1m && s < KN) sIdx[w][s] = jb4 + 1;
                s += b1m;
                if (b2m && s < KN) sIdx[w][s] = jb4 + 2;
                s += b2m;
                if (b3m && s < KN) sIdx[w][s] = jb4 + 3;
                count += __popc(m0) + __popc(m1) + __popc(m2) + __popc(m3);
                if (count >= KN) break;
            }
        }
        if (lane >= count) sIdx[w][lane] = firstidx;
        if (lane == 0) g_valid[q] = (count > 0) ? 1 : 0;
        __syncwarp();
        int j = sIdx[w][lane];
        __syncwarp();

        float x[19];
        x[0] = spc[j] - qx; x[1] = spc[NP + j] - qy; x[2] = spc[2 * NP + j] - qz;
        const float4* ft = (const float4*)(g_featT + ((size_t)b * NP + j) * CF);
        float4 f;
        f = ft[0]; x[3]  = f.x; x[4]  = f.y; x[5]  = f.z; x[6]  = f.w;
        f = ft[1]; x[7]  = f.x; x[8]  = f.y; x[9]  = f.z; x[10] = f.w;
        f = ft[2]; x[11] = f.x; x[12] = f.y; x[13] = f.z; x[14] = f.w;
        f = ft[3]; x[15] = f.x; x[16] = f.y; x[17] = f.z; x[18] = f.w;

        unsigned long long acc[16];
        #pragma unroll
        for (int c2 = 0; c2 < 16; c2++) acc[c2] = sbp[c2];
        #pragma unroll
        for (int i = 0; i < 19; i++) {
            unsigned long long xx = dup2(x[i]);
            const ulonglong2* wp = (const ulonglong2*)(swp + i * 16);
            #pragma unroll
            for (int c4 = 0; c4 < 8; c4++) {
                ulonglong2 wv = wp[c4];
                fma2(acc[2 * c4],     wv.x, xx);
                fma2(acc[2 * c4 + 1], wv.y, xx);
            }
        }
        float y[32], yq[32];
        #pragma unroll
        for (int c2 = 0; c2 < 16; c2++) {
            float2 u = unpack2(acc[c2]);
            y[2 * c2] = u.x; y[2 * c2 + 1] = u.y;
        }
        float4* dst = (float4*)(g_y1 + ((size_t)q * 32 + lane) * 32);
        #pragma unroll
        for (int c4 = 0; c4 < 8; c4++)
            dst[c4] = make_float4(y[4 * c4], y[4 * c4 + 1], y[4 * c4 + 2], y[4 * c4 + 3]);
        #pragma unroll
        for (int c = 0; c < 32; c++) yq[c] = y[c] * y[c];
        float osum, osq;
        warp_fold(y, yq, lane, osum, osq);
        atomicAdd(&bss[lane], osum);
        atomicAdd(&bsq[lane], osq);
    }
    __syncthreads();
    if (tid < 32) {
        atomicAdd(&g_stats[tid],      (double)bss[tid]);
        atomicAdd(&g_stats[32 + tid], (double)bsq[tid]);
    }
}

// ---------------- k2: BN1+ReLU + conv2 + stats2 (2ch x 2pt per thread) ------
// Weights staged k-major in smem: swt[k*32 + c] -> conflict-free lane reads.
__global__ __launch_bounds__(256) void k2_kernel(
    const float* __restrict__ w2, const float* __restrict__ b2,
    const float* __restrict__ gam, const float* __restrict__ bet)
{
    __shared__ float zp[256 * 32];      // [p][k] BN1+ReLU, 32 KB
    __shared__ float swt[1024];         // [k][c] transposed weights
    __shared__ float sa[32], sc[32];
    __shared__ float bss[32], bsq[32];
    int tid = threadIdx.x;
    if (tid < 32) {
        double m = g_stats[tid] * INVP;
        double v = g_stats[32 + tid] * INVP - m * m;
        double a = (double)gam[tid] / sqrt(v + EPSD);
        sa[tid] = (float)a;
        sc[tid] = (float)((double)bet[tid] - m * a);
        bss[tid] = 0.f; bsq[tid] = 0.f;
    }
    #pragma unroll
    for (int i = tid; i < 1024; i += 256) {
        int co = i >> 5, k = i & 31;     // w2[co][k], coalesced load
        swt[k * 32 + co] = w2[i];
    }
    __syncthreads();

    int p0 = blockIdx.x * 256;
    const float4* y4 = (const float4*)(g_y1 + (size_t)p0 * 32);
    float4* z4 = (float4*)zp;
    #pragma unroll
    for (int it = 0; it < 8; it++) {
        int lf = it * 256 + tid;                  // [0, 2048)
        int c0 = (lf & 7) * 4;
        float4 v = y4[lf];
        v.x = fmaxf(fmaf(sa[c0 + 0], v.x, sc[c0 + 0]), 0.f);
        v.y = fmaxf(fmaf(sa[c0 + 1], v.y, sc[c0 + 1]), 0.f);
        v.z = fmaxf(fmaf(sa[c0 + 2], v.z, sc[c0 + 2]), 0.f);
        v.w = fmaxf(fmaf(sa[c0 + 3], v.w, sc[c0 + 3]), 0.f);
        z4[lf] = v;
    }
    __syncthreads();

    int c  = tid & 15;                            // channels c, c+16
    int pg = tid >> 4;                            // 16 groups x 16 points
    unsigned long long wA[16], wB[16];
    #pragma unroll
    for (int k = 0; k < 16; k++) {                // conflict-free LDS.32
        wA[k] = pack2(swt[(2 * k) * 32 + c],      swt[(2 * k + 1) * 32 + c]);
        wB[k] = pack2(swt[(2 * k) * 32 + c + 16], swt[(2 * k + 1) * 32 + c + 16]);
    }
    float biasA = b2[c], biasB = b2[c + 16];

    float ss0 = 0.f, sq0 = 0.f, ss1 = 0.f, sq1 = 0.f;
    #pragma unroll 1
    for (int t = 0; t < 8; t++) {
        int pA = pg * 16 + 2 * t;
        const ulonglong2* rA = (const ulonglong2*)(zp + pA * 32);
        const ulonglong2* rB = (const ulonglong2*)(zp + (pA + 1) * 32);
        unsigned long long aCA = 0, aDA = 0, aCB = 0, aDB = 0;
        #pragma unroll
        for (int k = 0; k < 8; k++) {
            ulonglong2 lA = rA[k];
            ulonglong2 lB = rB[k];
            fma2(aCA, wA[2 * k],     lA.x);
            fma2(aDA, wB[2 * k],     lA.x);
            fma2(aCB, wA[2 * k],     lB.x);
            fma2(aDB, wB[2 * k],     lB.x);
            fma2(aCA, wA[2 * k + 1], lA.y);
            fma2(aDA, wB[2 * k + 1], lA.y);
            fma2(aCB, wA[2 * k + 1], lB.y);
            fma2(aDB, wB[2 * k + 1], lB.y);
        }
        float2 uCA = unpack2(aCA), uDA = unpack2(aDA);
        float2 uCB = unpack2(aCB), uDB = unpack2(aDB);
        float yCA = uCA.x + uCA.y + biasA;
        float yDA = uDA.x + uDA.y + biasB;
        float yCB = uCB.x + uCB.y + biasA;
        float yDB = uDB.x + uDB.y + biasB;
        size_t oA = (size_t)(p0 + pA) * 32;
        g_y2[oA + c]           = yCA;
        g_y2[oA + c + 16]      = yDA;
        g_y2[oA + 32 + c]      = yCB;
        g_y2[oA + 32 + c + 16] = yDB;
        ss0 += yCA + yCB; sq0 = fmaf(yCA, yCA, fmaf(yCB, yCB, sq0));
        ss1 += yDA + yDB; sq1 = fmaf(yDA, yDA, fmaf(yDB, yDB, sq1));
    }
    atomicAdd(&bss[c], ss0);      atomicAdd(&bsq[c], sq0);
    atomicAdd(&bss[c + 16], ss1); atomicAdd(&bsq[c + 16], sq1);
    __syncthreads();
    if (tid < 32) {
        atomicAdd(&g_stats[64 + tid], (double)bss[tid]);
        atomicAdd(&g_stats[96 + tid], (double)bsq[tid]);
    }
}

// ---------------- k3: BN2+ReLU + conv3 (32->64) + stats3 (2ch x 2pt) --------
// Weights staged k-major in smem: swt[k*64 + c] -> conflict-free lane reads.
__global__ __launch_bounds__(256) void k3_kernel(
    const float* __restrict__ w3, const float* __restrict__ b3,
    const float* __restrict__ gam, const float* __restrict__ bet)
{
    __shared__ float zp[256 * 32];      // 32 KB
    __shared__ float swt[2048];         // [k][c] transposed weights
    __shared__ float sa[32], sc[32];
    __shared__ float bss[64], bsq[64];
    int tid = threadIdx.x;
    if (tid < 32) {
        double m = g_stats[64 + tid] * INVP;
        double v = g_stats[96 + tid] * INVP - m * m;
        double a = (double)gam[tid] / sqrt(v + EPSD);
        sa[tid] = (float)a;
        sc[tid] = (float)((double)bet[tid] - m * a);
    }
    if (tid < 64) { bss[tid] = 0.f; bsq[tid] = 0.f; }
    #pragma unroll
    for (int i = tid; i < 2048; i += 256) {
        int co = i >> 5, k = i & 31;     // w3[co][k], coalesced load
        swt[k * 64 + co] = w3[i];
    }
    __syncthreads();

    int p0 = blockIdx.x * 256;
    const float4* y4 = (const float4*)(g_y2 + (size_t)p0 * 32);
    float4* z4 = (float4*)zp;
    #pragma unroll
    for (int it = 0; it < 8; it++) {
        int lf = it * 256 + tid;
        int c0 = (lf & 7) * 4;
        float4 v = y4[lf];
        v.x = fmaxf(fmaf(sa[c0 + 0], v.x, sc[c0 + 0]), 0.f);
        v.y = fmaxf(fmaf(sa[c0 + 1], v.y, sc[c0 + 1]), 0.f);
        v.z = fmaxf(fmaf(sa[c0 + 2], v.z, sc[c0 + 2]), 0.f);
        v.w = fmaxf(fmaf(sa[c0 + 3], v.w, sc[c0 + 3]), 0.f);
        z4[lf] = v;
    }
    __syncthreads();

    int c  = tid & 31;                            // channels c, c+32
    int pg = tid >> 5;                            // 8 groups x 32 points
    unsigned long long wA[16], wB[16];
    #pragma unroll
    for (int k = 0; k < 16; k++) {                // conflict-free LDS.32
        wA[k] = pack2(swt[(2 * k) * 64 + c],      swt[(2 * k + 1) * 64 + c]);
        wB[k] = pack2(swt[(2 * k) * 64 + c + 32], swt[(2 * k + 1) * 64 + c + 32]);
    }
    float biasA = b3[c], biasB = b3[c + 32];

    float ss0 = 0.f, sq0 = 0.f, ss1 = 0.f, sq1 = 0.f;
    #pragma unroll 1
    for (int t = 0; t < 16; t++) {
        int pA = pg * 32 + 2 * t;
        const ulonglong2* rA = (const ulonglong2*)(zp + pA * 32);
        const ulonglong2* rB = (const ulonglong2*)(zp + (pA + 1) * 32);
        unsigned long long aCA = 0, aDA = 0, aCB = 0, aDB = 0;
        #pragma unroll
        for (int k = 0; k < 8; k++) {
            ulonglong2 lA = rA[k];
            ulonglong2 lB = rB[k];
            fma2(aCA, wA[2 * k],     lA.x);
            fma2(aDA, wB[2 * k],     lA.x);
            fma2(aCB, wA[2 * k],     lB.x);
            fma2(aDB, wB[2 * k],     lB.x);
            fma2(aCA, wA[2 * k + 1], lA.y);
            fma2(aDA, wB[2 * k + 1], lA.y);
            fma2(aCB, wA[2 * k + 1], lB.y);
            fma2(aDB, wB[2 * k + 1], lB.y);
        }
        float2 uCA = unpack2(aCA), uDA = unpack2(aDA);
        float2 uCB = unpack2(aCB), uDB = unpack2(aDB);
        float yCA = uCA.x + uCA.y + biasA;
        float yDA = uDA.x + uDA.y + biasB;
        float yCB = uCB.x + uCB.y + biasA;
        float yDB = uDB.x + uDB.y + biasB;
        size_t oA = (size_t)(p0 + pA) * 64;
        g_y3[oA + c]           = yCA;
        g_y3[oA + c + 32]      = yDA;
        g_y3[oA + 64 + c]      = yCB;
        g_y3[oA + 64 + c + 32] = yDB;
        ss0 += yCA + yCB; sq0 = fmaf(yCA, yCA, fmaf(yCB, yCB, sq0));
        ss1 += yDA + yDB; sq1 = fmaf(yDA, yDA, fmaf(yDB, yDB, sq1));
    }
    atomicAdd(&bss[c], ss0);      atomicAdd(&bsq[c], sq0);
    atomicAdd(&bss[c + 32], ss1); atomicAdd(&bsq[c + 32], sq1);
    __syncthreads();
    if (tid < 64) {
        atomicAdd(&g_stats[128 + tid], (double)bss[tid]);
        atomicAdd(&g_stats[192 + tid], (double)bsq[tid]);
    }
}

// ---------------- k4: BN3+ReLU + valid mask + transpose to [B,64,S,K] ------
__global__ __launch_bounds__(256) void k4_kernel(
    float* __restrict__ out,
    const float* __restrict__ gam, const float* __restrict__ bet)
{
    __shared__ float tile[64 * 65];
    __shared__ float sa[64], sc[64];
    int tid = threadIdx.x;
    if (tid < 64) {
        double m = g_stats[128 + tid] * INVP;
        double v = g_stats[192 + tid] * INVP - m * m;
        double a = (double)gam[tid] / sqrt(v + EPSD);
        sa[tid] = (float)a;
        sc[tid] = (float)((double)bet[tid] - m * a);
    }
    __syncthreads();

    int pt0 = blockIdx.x * 64;
    int b   = pt0 >> 16;
    int w0  = pt0 & 65535;
    const float4* src4 = (const float4*)(g_y3 + (size_t)pt0 * 64);
    #pragma unroll
    for (int it = 0; it < 4; it++) {
        int lf = it * 256 + tid;                 // [0, 1024)
        int p = lf >> 4, c0 = (lf & 15) * 4;
        float4 v = src4[lf];
        float vm = (float)g_valid[(pt0 + p) >> 5];
        tile[p * 65 + c0 + 0] = fmaxf(fmaf(sa[c0 + 0], v.x, sc[c0 + 0]), 0.f) * vm;
        tile[p * 65 + c0 + 1] = fmaxf(fmaf(sa[c0 + 1], v.y, sc[c0 + 1]), 0.f) * vm;
        tile[p * 65 + c0 + 2] = fmaxf(fmaf(sa[c0 + 2], v.z, sc[c0 + 2]), 0.f) * vm;
        tile[p * 65 + c0 + 3] = fmaxf(fmaf(sa[c0 + 3], v.w, sc[c0 + 3]), 0.f) * vm;
    }
    __syncthreads();
    float* ob = out + (size_t)b * 64 * 65536 + w0;
    #pragma unroll
    for (int it = 0; it < 4; it++) {
        int lf = it * 256 + tid;
        int c = lf >> 4, pq = (lf & 15) * 4;
        float4 v = make_float4(tile[(pq + 0) * 65 + c], tile[(pq + 1) * 65 + c],
                               tile[(pq + 2) * 65 + c], tile[(pq + 3) * 65 + c]);
        *(float4*)(ob + (size_t)c * 65536 + pq) = v;
    }
}

// ---------------- launch ---------------------------------------------------
extern "C" void kernel_launch(void* const* d_in, const int* in_sizes, int n_in,
                              void* d_out, int out_size)
{
    const float* pc   = (const float*)d_in[0];
    const float* feat = (const float*)d_in[1];
    const float* npc  = (const float*)d_in[2];
    const float* w1   = (const float*)d_in[3];
    const float* b1   = (const float*)d_in[4];
    const float* g1   = (const float*)d_in[5];
    const float* be1  = (const float*)d_in[6];
    const float* w2   = (const float*)d_in[7];
    const float* b2   = (const float*)d_in[8];
    const float* g2   = (const float*)d_in[9];
    const float* be2  = (const float*)d_in[10];
    const float* w3   = (const float*)d_in[11];
    const float* b3   = (const float*)d_in[12];
    const float* g3   = (const float*)d_in[13];
    const float* be3  = (const float*)d_in[14];
    float* out = (float*)d_out;

    cudaFuncSetAttribute(k1_kernel, cudaFuncAttributeMaxDynamicSharedMemorySize,
                         3 * NP * sizeof(float));

    prep_kernel<<<512, 256>>>(feat);
    k1_kernel<<<256, 256, 3 * NP * sizeof(float)>>>(pc, npc, w1, b1);
    k2_kernel<<<1024, 256>>>(w2, b2, g1, be1);
    k3_kernel<<<1024, 256>>>(w3, b3, g2, be2);
    k4_kernel<<<4096, 256>>>(out, g3, be3);
}